// round 1
// baseline (speedup 1.0000x reference)
#include <cuda_runtime.h>

#define RBLK 1024
#define RTHR 256

__device__ float g_part[RBLK * 9];
__device__ float g_B[9];
__device__ float g_ref[3];

// ---------------------------------------------------------------------------
// Stage 1: 9-way reduction (sum x,y,z + 6 second moments) over T samples.
// fp32 per-thread partials (~16 elements each -> negligible rounding),
// warp-shuffle tree reduce, per-block float partials to g_part.
// ---------------------------------------------------------------------------
__global__ void reduce_vec_kernel(const float* __restrict__ x, int T) {
    int n4 = T >> 2;
    const float4* X = (const float4*)x;

    float s[9];
#pragma unroll
    for (int k = 0; k < 9; k++) s[k] = 0.f;

    for (int i = blockIdx.x * blockDim.x + threadIdx.x; i < n4;
         i += gridDim.x * blockDim.x) {
        float4 a = X[i];
        float4 b = X[n4 + i];
        float4 c = X[2 * n4 + i];
#define ACC(ax, bx, cx)                                   \
        s[0] += (ax); s[1] += (bx); s[2] += (cx);         \
        s[3] += (ax)*(ax); s[4] += (ax)*(bx);             \
        s[5] += (ax)*(cx); s[6] += (bx)*(bx);             \
        s[7] += (bx)*(cx); s[8] += (cx)*(cx);
        ACC(a.x, b.x, c.x); ACC(a.y, b.y, c.y);
        ACC(a.z, b.z, c.z); ACC(a.w, b.w, c.w);
#undef ACC
    }

    int lane = threadIdx.x & 31, wid = threadIdx.x >> 5;
#pragma unroll
    for (int off = 16; off; off >>= 1)
#pragma unroll
        for (int k = 0; k < 9; k++)
            s[k] += __shfl_down_sync(0xffffffffu, s[k], off);

    __shared__ float sh[RTHR / 32][9];
    if (lane == 0)
#pragma unroll
        for (int k = 0; k < 9; k++) sh[wid][k] = s[k];
    __syncthreads();
    if (wid == 0) {
#pragma unroll
        for (int k = 0; k < 9; k++)
            s[k] = (lane < RTHR / 32) ? sh[lane][k] : 0.f;
#pragma unroll
        for (int off = 4; off; off >>= 1)
#pragma unroll
            for (int k = 0; k < 9; k++)
                s[k] += __shfl_down_sync(0xffffffffu, s[k], off);
        if (lane == 0)
#pragma unroll
            for (int k = 0; k < 9; k++)
                g_part[blockIdx.x * 9 + k] = s[k];
    }
}

// Scalar fallback (only used when T % 4 != 0)
__global__ void reduce_sca_kernel(const float* __restrict__ x, int T) {
    float s[9];
#pragma unroll
    for (int k = 0; k < 9; k++) s[k] = 0.f;
    for (int t = blockIdx.x * blockDim.x + threadIdx.x; t < T;
         t += gridDim.x * blockDim.x) {
        float ax = x[t], bx = x[(size_t)T + t], cx = x[2 * (size_t)T + t];
        s[0]+=ax; s[1]+=bx; s[2]+=cx; s[3]+=ax*ax; s[4]+=ax*bx;
        s[5]+=ax*cx; s[6]+=bx*bx; s[7]+=bx*cx; s[8]+=cx*cx;
    }
    int lane = threadIdx.x & 31, wid = threadIdx.x >> 5;
#pragma unroll
    for (int off = 16; off; off >>= 1)
#pragma unroll
        for (int k = 0; k < 9; k++)
            s[k] += __shfl_down_sync(0xffffffffu, s[k], off);
    __shared__ float sh[RTHR / 32][9];
    if (lane == 0)
#pragma unroll
        for (int k = 0; k < 9; k++) sh[wid][k] = s[k];
    __syncthreads();
    if (wid == 0) {
#pragma unroll
        for (int k = 0; k < 9; k++)
            s[k] = (lane < RTHR / 32) ? sh[lane][k] : 0.f;
#pragma unroll
        for (int off = 4; off; off >>= 1)
#pragma unroll
            for (int k = 0; k < 9; k++)
                s[k] += __shfl_down_sync(0xffffffffu, s[k], off);
        if (lane == 0)
#pragma unroll
            for (int k = 0; k < 9; k++)
                g_part[blockIdx.x * 9 + k] = s[k];
    }
}

// ---------------------------------------------------------------------------
// Compensated (twoSum) fp32 accumulation — avoids bulk fp64 on B300
// ---------------------------------------------------------------------------
struct KS { float s, c; };

__device__ __forceinline__ void ks_add(KS& a, float v) {
    float t  = a.s + v;
    float bp = t - a.s;
    float err = (a.s - (t - bp)) + (v - bp);
    a.c += err;
    a.s  = t;
}
__device__ __forceinline__ KS ks_comb(KS a, float s2, float c2) {
    float t  = a.s + s2;
    float bp = t - a.s;
    float err = (a.s - (t - bp)) + (s2 - bp);
    KS r; r.s = t; r.c = a.c + c2 + err;
    return r;
}

// ---------------------------------------------------------------------------
// Stage 2: final sum (compensated fp32), 3x3 covariance, Jacobi eigensolve
// in fp64 (tiny op count, thread 0 only), basis construction.
// ---------------------------------------------------------------------------
__global__ void solve_kernel(const float* __restrict__ x,
                             const float* __restrict__ axis, int T) {
    int tid = threadIdx.x;
    KS acc[9];
#pragma unroll
    for (int k = 0; k < 9; k++) { acc[k].s = 0.f; acc[k].c = 0.f; }

    for (int b = tid; b < RBLK; b += 256)
#pragma unroll
        for (int k = 0; k < 9; k++) ks_add(acc[k], g_part[b * 9 + k]);

    int lane = tid & 31, wid = tid >> 5;
#pragma unroll
    for (int off = 16; off; off >>= 1)
#pragma unroll
        for (int k = 0; k < 9; k++) {
            float s2 = __shfl_down_sync(0xffffffffu, acc[k].s, off);
            float c2 = __shfl_down_sync(0xffffffffu, acc[k].c, off);
            acc[k] = ks_comb(acc[k], s2, c2);
        }

    __shared__ float shs[8][9], shc[8][9];
    if (lane == 0)
#pragma unroll
        for (int k = 0; k < 9; k++) { shs[wid][k] = acc[k].s; shc[wid][k] = acc[k].c; }
    __syncthreads();

    if (tid == 0) {
        double S[9];
#pragma unroll
        for (int k = 0; k < 9; k++) {
            double v = 0.0;
            for (int w = 0; w < 8; w++)
                v += (double)shs[w][k] + (double)shc[w][k];
            S[k] = v;
        }
        double dT = (double)T;
        double mu0 = S[0] / dT, mu1 = S[1] / dT, mu2 = S[2] / dT;
        double A[3][3];
        A[0][0] = (S[3] - dT * mu0 * mu0) / (dT - 1.0);
        A[0][1] = A[1][0] = (S[4] - dT * mu0 * mu1) / (dT - 1.0);
        A[0][2] = A[2][0] = (S[5] - dT * mu0 * mu2) / (dT - 1.0);
        A[1][1] = (S[6] - dT * mu1 * mu1) / (dT - 1.0);
        A[1][2] = A[2][1] = (S[7] - dT * mu1 * mu2) / (dT - 1.0);
        A[2][2] = (S[8] - dT * mu2 * mu2) / (dT - 1.0);

        double V[3][3] = {{1,0,0},{0,1,0},{0,0,1}};
        for (int sweep = 0; sweep < 8; sweep++) {
            for (int p = 0; p < 2; p++)
                for (int q = p + 1; q < 3; q++) {
                    double apq = A[p][q];
                    if (fabs(apq) < 1e-300) continue;
                    double tau = (A[q][q] - A[p][p]) / (2.0 * apq);
                    double t = ((tau >= 0.0) ? 1.0 : -1.0) /
                               (fabs(tau) + sqrt(1.0 + tau * tau));
                    double cth = 1.0 / sqrt(1.0 + t * t);
                    double sth = t * cth;
                    for (int r = 0; r < 3; r++) {
                        double arp = A[r][p], arq = A[r][q];
                        A[r][p] = cth * arp - sth * arq;
                        A[r][q] = sth * arp + cth * arq;
                    }
                    for (int cc = 0; cc < 3; cc++) {
                        double apc = A[p][cc], aqc = A[q][cc];
                        A[p][cc] = cth * apc - sth * aqc;
                        A[q][cc] = sth * apc + cth * aqc;
                    }
                    for (int r = 0; r < 3; r++) {
                        double vrp = V[r][p], vrq = V[r][q];
                        V[r][p] = cth * vrp - sth * vrq;
                        V[r][q] = sth * vrp + cth * vrq;
                    }
                }
        }
        int im = 0;
        if (A[1][1] > A[0][0]) im = 1;
        if (A[2][2] > A[im][im]) im = 2;
        double zx = V[0][im], zy = V[1][im], zz = V[2][im];

        // ZFwd = quat_vec_mul(Qrot, [0,0,1]); Qrot = x[3:7, t=0] (raw, unnormalized)
        double qx = (double)x[3 * (size_t)T];
        double qy = (double)x[4 * (size_t)T];
        double qz = (double)x[5 * (size_t)T];
        double qw = (double)x[6 * (size_t)T];
        double fx = 2.0 * (qx * qz + qw * qy);
        double fy = 2.0 * (qy * qz - qw * qx);
        double fz = 1.0 - 2.0 * (qx * qx + qy * qy);
        if (fx * zx + fy * zy + fz * zz < 0.0) { zx = -zx; zy = -zy; zz = -zz; }

        double ux = (double)axis[0], uy = (double)axis[1], uz = (double)axis[2];
        double rx = uy * zz - uz * zy;                 // right = up x z
        double ry = uz * zx - ux * zz;
        double rz = ux * zy - uy * zx;
        double fwx = ry * uz - rz * uy;                // fwd = right x up
        double fwy = rz * ux - rx * uz;
        double fwz = rx * uy - ry * ux;

        g_B[0] = (float)rx;  g_B[1] = (float)ry;  g_B[2] = (float)rz;
        g_B[3] = (float)ux;  g_B[4] = (float)uy;  g_B[5] = (float)uz;
        g_B[6] = (float)fwx; g_B[7] = (float)fwy; g_B[8] = (float)fwz;
        g_ref[0] = x[0]; g_ref[1] = x[(size_t)T]; g_ref[2] = x[2 * (size_t)T];
    }
}

// ---------------------------------------------------------------------------
// Stage 3: streaming affine transform + Add copy. 96 MB in / 96 MB out.
// ---------------------------------------------------------------------------
__global__ void transform_vec_kernel(const float* __restrict__ x,
                                     float* __restrict__ out, int T) {
    int n4 = T >> 2;
    int i = blockIdx.x * blockDim.x + threadIdx.x;
    if (i >= n4) return;

    float b00 = g_B[0], b01 = g_B[1], b02 = g_B[2];
    float b10 = g_B[3], b11 = g_B[4], b12 = g_B[5];
    float b20 = g_B[6], b21 = g_B[7], b22 = g_B[8];
    float r0 = g_ref[0], r1 = g_ref[1], r2 = g_ref[2];

    const float4* X = (const float4*)x;
    float4* O = (float4*)out;

    float4 p0 = X[i], p1 = X[n4 + i], p2 = X[2 * n4 + i];
    float4 a0 = X[7 * n4 + i], a1 = X[8 * n4 + i], a2 = X[9 * n4 + i];
    float4 o0, o1, o2;
#define TR(f) {                                         \
    float dx = p0.f - r0, dy = p1.f - r1, dz = p2.f - r2; \
    o0.f = b00 * dx + b01 * dy + b02 * dz;              \
    o1.f = b10 * dx + b11 * dy + b12 * dz;              \
    o2.f = b20 * dx + b21 * dy + b22 * dz; }
    TR(x); TR(y); TR(z); TR(w);
#undef TR
    O[i]          = o0;
    O[n4 + i]     = o1;
    O[2 * n4 + i] = o2;
    O[3 * n4 + i] = a0;
    O[4 * n4 + i] = a1;
    O[5 * n4 + i] = a2;
}

__global__ void transform_sca_kernel(const float* __restrict__ x,
                                     float* __restrict__ out, int T) {
    size_t sT = (size_t)T;
    float b00 = g_B[0], b01 = g_B[1], b02 = g_B[2];
    float b10 = g_B[3], b11 = g_B[4], b12 = g_B[5];
    float b20 = g_B[6], b21 = g_B[7], b22 = g_B[8];
    float r0 = g_ref[0], r1 = g_ref[1], r2 = g_ref[2];
    for (int t = blockIdx.x * blockDim.x + threadIdx.x; t < T;
         t += gridDim.x * blockDim.x) {
        float dx = x[t] - r0, dy = x[sT + t] - r1, dz = x[2 * sT + t] - r2;
        out[t]          = b00 * dx + b01 * dy + b02 * dz;
        out[sT + t]     = b10 * dx + b11 * dy + b12 * dz;
        out[2 * sT + t] = b20 * dx + b21 * dy + b22 * dz;
        out[3 * sT + t] = x[7 * sT + t];
        out[4 * sT + t] = x[8 * sT + t];
        out[5 * sT + t] = x[9 * sT + t];
    }
}

extern "C" void kernel_launch(void* const* d_in, const int* in_sizes, int n_in,
                              void* d_out, int out_size) {
    const float* x = (const float*)d_in[0];
    const float* axis = (const float*)d_in[1];
    int T = in_sizes[0] / 10;

    if ((T & 3) == 0) {
        reduce_vec_kernel<<<RBLK, RTHR>>>(x, T);
        solve_kernel<<<1, 256>>>(x, axis, T);
        int n4 = T >> 2;
        int blocks = (n4 + 255) / 256;
        transform_vec_kernel<<<blocks, 256>>>(x, (float*)d_out, T);
    } else {
        reduce_sca_kernel<<<RBLK, RTHR>>>(x, T);
        solve_kernel<<<1, 256>>>(x, axis, T);
        int blocks = (T + 255) / 256;
        if (blocks > 16384) blocks = 16384;
        transform_sca_kernel<<<blocks, 256>>>(x, (float*)d_out, T);
    }
}

// round 4
// speedup vs baseline: 2.3427x; 2.3427x over previous
#include <cuda_runtime.h>

#define RBLK 1024
#define RTHR 256

__device__ float g_part[RBLK * 9];
__device__ float g_B[9];
__device__ float g_ref[3];

// ---------------------------------------------------------------------------
// Stage 1: 9-way reduction (sum x,y,z + 6 second moments) over T samples.
// ---------------------------------------------------------------------------
__global__ void reduce_vec_kernel(const float* __restrict__ x, int T) {
    int n4 = T >> 2;
    const float4* X = (const float4*)x;

    float s[9];
#pragma unroll
    for (int k = 0; k < 9; k++) s[k] = 0.f;

    for (int i = blockIdx.x * blockDim.x + threadIdx.x; i < n4;
         i += gridDim.x * blockDim.x) {
        float4 a = X[i];
        float4 b = X[n4 + i];
        float4 c = X[2 * n4 + i];
#define ACC(ax, bx, cx)                                   \
        s[0] += (ax); s[1] += (bx); s[2] += (cx);         \
        s[3] += (ax)*(ax); s[4] += (ax)*(bx);             \
        s[5] += (ax)*(cx); s[6] += (bx)*(bx);             \
        s[7] += (bx)*(cx); s[8] += (cx)*(cx);
        ACC(a.x, b.x, c.x); ACC(a.y, b.y, c.y);
        ACC(a.z, b.z, c.z); ACC(a.w, b.w, c.w);
#undef ACC
    }

    int lane = threadIdx.x & 31, wid = threadIdx.x >> 5;
#pragma unroll
    for (int off = 16; off; off >>= 1)
#pragma unroll
        for (int k = 0; k < 9; k++)
            s[k] += __shfl_down_sync(0xffffffffu, s[k], off);

    __shared__ float sh[RTHR / 32][9];
    if (lane == 0)
#pragma unroll
        for (int k = 0; k < 9; k++) sh[wid][k] = s[k];
    __syncthreads();
    if (wid == 0) {
#pragma unroll
        for (int k = 0; k < 9; k++)
            s[k] = (lane < RTHR / 32) ? sh[lane][k] : 0.f;
#pragma unroll
        for (int off = 4; off; off >>= 1)
#pragma unroll
            for (int k = 0; k < 9; k++)
                s[k] += __shfl_down_sync(0xffffffffu, s[k], off);
        if (lane == 0)
#pragma unroll
            for (int k = 0; k < 9; k++)
                g_part[blockIdx.x * 9 + k] = s[k];
    }
}

__global__ void reduce_sca_kernel(const float* __restrict__ x, int T) {
    float s[9];
#pragma unroll
    for (int k = 0; k < 9; k++) s[k] = 0.f;
    for (int t = blockIdx.x * blockDim.x + threadIdx.x; t < T;
         t += gridDim.x * blockDim.x) {
        float ax = x[t], bx = x[(size_t)T + t], cx = x[2 * (size_t)T + t];
        s[0]+=ax; s[1]+=bx; s[2]+=cx; s[3]+=ax*ax; s[4]+=ax*bx;
        s[5]+=ax*cx; s[6]+=bx*bx; s[7]+=bx*cx; s[8]+=cx*cx;
    }
    int lane = threadIdx.x & 31, wid = threadIdx.x >> 5;
#pragma unroll
    for (int off = 16; off; off >>= 1)
#pragma unroll
        for (int k = 0; k < 9; k++)
            s[k] += __shfl_down_sync(0xffffffffu, s[k], off);
    __shared__ float sh[RTHR / 32][9];
    if (lane == 0)
#pragma unroll
        for (int k = 0; k < 9; k++) sh[wid][k] = s[k];
    __syncthreads();
    if (wid == 0) {
#pragma unroll
        for (int k = 0; k < 9; k++)
            s[k] = (lane < RTHR / 32) ? sh[lane][k] : 0.f;
#pragma unroll
        for (int off = 4; off; off >>= 1)
#pragma unroll
            for (int k = 0; k < 9; k++)
                s[k] += __shfl_down_sync(0xffffffffu, s[k], off);
        if (lane == 0)
#pragma unroll
            for (int k = 0; k < 9; k++)
                g_part[blockIdx.x * 9 + k] = s[k];
    }
}

// ---------------------------------------------------------------------------
// Compensated fp32 accumulation
// ---------------------------------------------------------------------------
struct KS { float s, c; };

__device__ __forceinline__ void ks_add(KS& a, float v) {
    float t  = a.s + v;
    float bp = t - a.s;
    float err = (a.s - (t - bp)) + (v - bp);
    a.c += err;
    a.s  = t;
}
__device__ __forceinline__ KS ks_comb(KS a, float s2, float c2) {
    float t  = a.s + s2;
    float bp = t - a.s;
    float err = (a.s - (t - bp)) + (s2 - bp);
    KS r; r.s = t; r.c = a.c + c2 + err;
    return r;
}

// ---------------------------------------------------------------------------
// Stage 2: final sum, covariance in fp64 (~30 ops), then SCALED fp32 Jacobi.
// The eigenvectors of A equal those of (A - shift*I)/scale; after scaling the
// deviator is O(1) so fp32 gives ~1e-7 vector error with MUFU-speed math.
// ---------------------------------------------------------------------------
__global__ void solve_kernel(const float* __restrict__ x,
                             const float* __restrict__ axis, int T) {
    int tid = threadIdx.x;
    KS acc[9];
#pragma unroll
    for (int k = 0; k < 9; k++) { acc[k].s = 0.f; acc[k].c = 0.f; }

    for (int b = tid; b < RBLK; b += 256)
#pragma unroll
        for (int k = 0; k < 9; k++) ks_add(acc[k], g_part[b * 9 + k]);

    int lane = tid & 31, wid = tid >> 5;
#pragma unroll
    for (int off = 16; off; off >>= 1)
#pragma unroll
        for (int k = 0; k < 9; k++) {
            float s2 = __shfl_down_sync(0xffffffffu, acc[k].s, off);
            float c2 = __shfl_down_sync(0xffffffffu, acc[k].c, off);
            acc[k] = ks_comb(acc[k], s2, c2);
        }

    __shared__ float shs[8][9], shc[8][9];
    if (lane == 0)
#pragma unroll
        for (int k = 0; k < 9; k++) { shs[wid][k] = acc[k].s; shc[wid][k] = acc[k].c; }
    __syncthreads();

    if (tid == 0) {
        double S[9];
#pragma unroll
        for (int k = 0; k < 9; k++) {
            double v = 0.0;
            for (int w = 0; w < 8; w++)
                v += (double)shs[w][k] + (double)shc[w][k];
            S[k] = v;
        }
        double dT = (double)T;
        double mu0 = S[0] / dT, mu1 = S[1] / dT, mu2 = S[2] / dT;
        double c00 = (S[3] - dT * mu0 * mu0);
        double c01 = (S[4] - dT * mu0 * mu1);
        double c02 = (S[5] - dT * mu0 * mu2);
        double c11 = (S[6] - dT * mu1 * mu1);
        double c12 = (S[7] - dT * mu1 * mu2);
        double c22 = (S[8] - dT * mu2 * mu2);
        // (dividing by T-1 is a positive scale: eigenvectors unchanged; skip it)

        // Deviator: subtract trace/3 (eigenvectors unchanged), then scale to O(1)
        double sh3 = (c00 + c11 + c22) * (1.0 / 3.0);
        double d00 = c00 - sh3, d11 = c11 - sh3, d22 = c22 - sh3;
        double mx = fabs(d00);
        if (fabs(d11) > mx) mx = fabs(d11);
        if (fabs(d22) > mx) mx = fabs(d22);
        if (fabs(c01) > mx) mx = fabs(c01);
        if (fabs(c02) > mx) mx = fabs(c02);
        if (fabs(c12) > mx) mx = fabs(c12);
        double inv = (mx > 0.0) ? (1.0 / mx) : 1.0;

        float A[3][3];
        A[0][0] = (float)(d00 * inv);
        A[1][1] = (float)(d11 * inv);
        A[2][2] = (float)(d22 * inv);
        A[0][1] = A[1][0] = (float)(c01 * inv);
        A[0][2] = A[2][0] = (float)(c02 * inv);
        A[1][2] = A[2][1] = (float)(c12 * inv);

        float V[3][3] = {{1,0,0},{0,1,0},{0,0,1}};
#pragma unroll 1
        for (int sweep = 0; sweep < 7; sweep++) {
            for (int p = 0; p < 2; p++)
                for (int q = p + 1; q < 3; q++) {
                    float apq = A[p][q];
                    if (fabsf(apq) < 1e-30f) continue;
                    float tau = (A[q][q] - A[p][p]) / (2.0f * apq);
                    float t = ((tau >= 0.0f) ? 1.0f : -1.0f) /
                              (fabsf(tau) + sqrtf(1.0f + tau * tau));
                    float cth = rsqrtf(1.0f + t * t);
                    float sth = t * cth;
                    for (int r = 0; r < 3; r++) {
                        float arp = A[r][p], arq = A[r][q];
                        A[r][p] = cth * arp - sth * arq;
                        A[r][q] = sth * arp + cth * arq;
                    }
                    for (int cc = 0; cc < 3; cc++) {
                        float apc = A[p][cc], aqc = A[q][cc];
                        A[p][cc] = cth * apc - sth * aqc;
                        A[q][cc] = sth * apc + cth * aqc;
                    }
                    for (int r = 0; r < 3; r++) {
                        float vrp = V[r][p], vrq = V[r][q];
                        V[r][p] = cth * vrp - sth * vrq;
                        V[r][q] = sth * vrp + cth * vrq;
                    }
                }
        }
        int im = 0;
        if (A[1][1] > A[0][0]) im = 1;
        if (A[2][2] > A[im][im]) im = 2;
        float zx = V[0][im], zy = V[1][im], zz = V[2][im];

        // ZFwd from raw quaternion at t=0
        float qx = x[3 * (size_t)T];
        float qy = x[4 * (size_t)T];
        float qz = x[5 * (size_t)T];
        float qw = x[6 * (size_t)T];
        float fx = 2.0f * (qx * qz + qw * qy);
        float fy = 2.0f * (qy * qz - qw * qx);
        float fz = 1.0f - 2.0f * (qx * qx + qy * qy);
        if (fx * zx + fy * zy + fz * zz < 0.0f) { zx = -zx; zy = -zy; zz = -zz; }

        float ux = axis[0], uy = axis[1], uz = axis[2];
        float rx = uy * zz - uz * zy;                 // right = up x z
        float ry = uz * zx - ux * zz;
        float rz = ux * zy - uy * zx;
        float fwx = ry * uz - rz * uy;                // fwd = right x up
        float fwy = rz * ux - rx * uz;
        float fwz = rx * uy - ry * ux;

        g_B[0] = rx;  g_B[1] = ry;  g_B[2] = rz;
        g_B[3] = ux;  g_B[4] = uy;  g_B[5] = uz;
        g_B[6] = fwx; g_B[7] = fwy; g_B[8] = fwz;
        g_ref[0] = x[0]; g_ref[1] = x[(size_t)T]; g_ref[2] = x[2 * (size_t)T];
    }
}

// ---------------------------------------------------------------------------
// Stage 3: streaming affine transform + Add copy, 2 float4 per stream per
// thread (MLP_p1=12), streaming loads/stores (no reuse).
// ---------------------------------------------------------------------------
__global__ void transform_vec_kernel(const float* __restrict__ x,
                                     float* __restrict__ out, int T) {
    int n4 = T >> 2;
    int base = (blockIdx.x * blockDim.x + threadIdx.x) * 2;
    if (base >= n4) return;
    int cnt = (base + 1 < n4) ? 2 : 1;

    float b00 = g_B[0], b01 = g_B[1], b02 = g_B[2];
    float b10 = g_B[3], b11 = g_B[4], b12 = g_B[5];
    float b20 = g_B[6], b21 = g_B[7], b22 = g_B[8];
    float r0 = g_ref[0], r1 = g_ref[1], r2 = g_ref[2];

    const float4* X = (const float4*)x;
    float4* O = (float4*)out;

    float4 p0[2], p1[2], p2[2], a0[2], a1[2], a2[2];
#pragma unroll
    for (int u = 0; u < 2; u++) {
        if (u >= cnt) break;
        int i = base + u;
        p0[u] = __ldcs(&X[i]);
        p1[u] = __ldcs(&X[n4 + i]);
        p2[u] = __ldcs(&X[2 * n4 + i]);
        a0[u] = __ldcs(&X[7 * n4 + i]);
        a1[u] = __ldcs(&X[8 * n4 + i]);
        a2[u] = __ldcs(&X[9 * n4 + i]);
    }
#pragma unroll
    for (int u = 0; u < 2; u++) {
        if (u >= cnt) break;
        int i = base + u;
        float4 o0, o1, o2;
#define TR(f) {                                                    \
        float dx = p0[u].f - r0, dy = p1[u].f - r1, dz = p2[u].f - r2; \
        o0.f = b00 * dx + b01 * dy + b02 * dz;                     \
        o1.f = b10 * dx + b11 * dy + b12 * dz;                     \
        o2.f = b20 * dx + b21 * dy + b22 * dz; }
        TR(x); TR(y); TR(z); TR(w);
#undef TR
        __stcs(&O[i],          o0);
        __stcs(&O[n4 + i],     o1);
        __stcs(&O[2 * n4 + i], o2);
        __stcs(&O[3 * n4 + i], a0[u]);
        __stcs(&O[4 * n4 + i], a1[u]);
        __stcs(&O[5 * n4 + i], a2[u]);
    }
}

__global__ void transform_sca_kernel(const float* __restrict__ x,
                                     float* __restrict__ out, int T) {
    size_t sT = (size_t)T;
    float b00 = g_B[0], b01 = g_B[1], b02 = g_B[2];
    float b10 = g_B[3], b11 = g_B[4], b12 = g_B[5];
    float b20 = g_B[6], b21 = g_B[7], b22 = g_B[8];
    float r0 = g_ref[0], r1 = g_ref[1], r2 = g_ref[2];
    for (int t = blockIdx.x * blockDim.x + threadIdx.x; t < T;
         t += gridDim.x * blockDim.x) {
        float dx = x[t] - r0, dy = x[sT + t] - r1, dz = x[2 * sT + t] - r2;
        out[t]          = b00 * dx + b01 * dy + b02 * dz;
        out[sT + t]     = b10 * dx + b11 * dy + b12 * dz;
        out[2 * sT + t] = b20 * dx + b21 * dy + b22 * dz;
        out[3 * sT + t] = x[7 * sT + t];
        out[4 * sT + t] = x[8 * sT + t];
        out[5 * sT + t] = x[9 * sT + t];
    }
}

extern "C" void kernel_launch(void* const* d_in, const int* in_sizes, int n_in,
                              void* d_out, int out_size) {
    const float* x = (const float*)d_in[0];
    const float* axis = (const float*)d_in[1];
    int T = in_sizes[0] / 10;

    if ((T & 3) == 0) {
        reduce_vec_kernel<<<RBLK, RTHR>>>(x, T);
        solve_kernel<<<1, 256>>>(x, axis, T);
        int n4 = T >> 2;
        int threads = (n4 + 1) / 2;
        int blocks = (threads + 255) / 256;
        transform_vec_kernel<<<blocks, 256>>>(x, (float*)d_out, T);
    } else {
        reduce_sca_kernel<<<RBLK, RTHR>>>(x, T);
        solve_kernel<<<1, 256>>>(x, axis, T);
        int blocks = (T + 255) / 256;
        if (blocks > 16384) blocks = 16384;
        transform_sca_kernel<<<blocks, 256>>>(x, (float*)d_out, T);
    }
}

// round 5
// speedup vs baseline: 2.3731x; 1.0130x over previous
#include <cuda_runtime.h>

#define RBLK 1024
#define RTHR 256

__device__ float g_part[RBLK * 9];
__device__ float g_B[9];
__device__ float g_ref[3];

// ---------------------------------------------------------------------------
// Stage 1: 9-way reduction. Each thread handles a contiguous pair of float4
// per stream (6 front-batched LDG.128 -> deeper L1tex queue / higher MLP).
// Default caching so rows 0-2 remain L2-resident for the transform pass.
// ---------------------------------------------------------------------------
__global__ void reduce_vec_kernel(const float* __restrict__ x, int T) {
    int n4 = T >> 2;
    const float4* X = (const float4*)x;

    float s[9];
#pragma unroll
    for (int k = 0; k < 9; k++) s[k] = 0.f;

    int tid = blockIdx.x * blockDim.x + threadIdx.x;
    int stride = gridDim.x * blockDim.x;

    int i = tid * 2;
    for (; i + 1 < n4; i += stride * 2) {
        float4 a0 = X[i],          a1 = X[i + 1];
        float4 b0 = X[n4 + i],     b1 = X[n4 + i + 1];
        float4 c0 = X[2 * n4 + i], c1 = X[2 * n4 + i + 1];
#define ACC(ax, bx, cx)                                   \
        s[0] += (ax); s[1] += (bx); s[2] += (cx);         \
        s[3] += (ax)*(ax); s[4] += (ax)*(bx);             \
        s[5] += (ax)*(cx); s[6] += (bx)*(bx);             \
        s[7] += (bx)*(cx); s[8] += (cx)*(cx);
        ACC(a0.x, b0.x, c0.x); ACC(a0.y, b0.y, c0.y);
        ACC(a0.z, b0.z, c0.z); ACC(a0.w, b0.w, c0.w);
        ACC(a1.x, b1.x, c1.x); ACC(a1.y, b1.y, c1.y);
        ACC(a1.z, b1.z, c1.z); ACC(a1.w, b1.w, c1.w);
    }
    if (i < n4) {  // odd tail element
        float4 a0 = X[i];
        float4 b0 = X[n4 + i];
        float4 c0 = X[2 * n4 + i];
        ACC(a0.x, b0.x, c0.x); ACC(a0.y, b0.y, c0.y);
        ACC(a0.z, b0.z, c0.z); ACC(a0.w, b0.w, c0.w);
#undef ACC
    }

    int lane = threadIdx.x & 31, wid = threadIdx.x >> 5;
#pragma unroll
    for (int off = 16; off; off >>= 1)
#pragma unroll
        for (int k = 0; k < 9; k++)
            s[k] += __shfl_down_sync(0xffffffffu, s[k], off);

    __shared__ float sh[RTHR / 32][9];
    if (lane == 0)
#pragma unroll
        for (int k = 0; k < 9; k++) sh[wid][k] = s[k];
    __syncthreads();
    if (wid == 0) {
#pragma unroll
        for (int k = 0; k < 9; k++)
            s[k] = (lane < RTHR / 32) ? sh[lane][k] : 0.f;
#pragma unroll
        for (int off = 4; off; off >>= 1)
#pragma unroll
            for (int k = 0; k < 9; k++)
                s[k] += __shfl_down_sync(0xffffffffu, s[k], off);
        if (lane == 0)
#pragma unroll
            for (int k = 0; k < 9; k++)
                g_part[blockIdx.x * 9 + k] = s[k];
    }
}

__global__ void reduce_sca_kernel(const float* __restrict__ x, int T) {
    float s[9];
#pragma unroll
    for (int k = 0; k < 9; k++) s[k] = 0.f;
    for (int t = blockIdx.x * blockDim.x + threadIdx.x; t < T;
         t += gridDim.x * blockDim.x) {
        float ax = x[t], bx = x[(size_t)T + t], cx = x[2 * (size_t)T + t];
        s[0]+=ax; s[1]+=bx; s[2]+=cx; s[3]+=ax*ax; s[4]+=ax*bx;
        s[5]+=ax*cx; s[6]+=bx*bx; s[7]+=bx*cx; s[8]+=cx*cx;
    }
    int lane = threadIdx.x & 31, wid = threadIdx.x >> 5;
#pragma unroll
    for (int off = 16; off; off >>= 1)
#pragma unroll
        for (int k = 0; k < 9; k++)
            s[k] += __shfl_down_sync(0xffffffffu, s[k], off);
    __shared__ float sh[RTHR / 32][9];
    if (lane == 0)
#pragma unroll
        for (int k = 0; k < 9; k++) sh[wid][k] = s[k];
    __syncthreads();
    if (wid == 0) {
#pragma unroll
        for (int k = 0; k < 9; k++)
            s[k] = (lane < RTHR / 32) ? sh[lane][k] : 0.f;
#pragma unroll
        for (int off = 4; off; off >>= 1)
#pragma unroll
            for (int k = 0; k < 9; k++)
                s[k] += __shfl_down_sync(0xffffffffu, s[k], off);
        if (lane == 0)
#pragma unroll
            for (int k = 0; k < 9; k++)
                g_part[blockIdx.x * 9 + k] = s[k];
    }
}

// ---------------------------------------------------------------------------
// Compensated fp32 accumulation
// ---------------------------------------------------------------------------
struct KS { float s, c; };

__device__ __forceinline__ void ks_add(KS& a, float v) {
    float t  = a.s + v;
    float bp = t - a.s;
    float err = (a.s - (t - bp)) + (v - bp);
    a.c += err;
    a.s  = t;
}
__device__ __forceinline__ KS ks_comb(KS a, float s2, float c2) {
    float t  = a.s + s2;
    float bp = t - a.s;
    float err = (a.s - (t - bp)) + (s2 - bp);
    KS r; r.s = t; r.c = a.c + c2 + err;
    return r;
}

// ---------------------------------------------------------------------------
// Stage 2: final sum; covariance with only 2 fp64 divides; scaled fp32
// Jacobi (4 sweeps — deviator off-diag is tiny, quadratic convergence).
// ---------------------------------------------------------------------------
__global__ void solve_kernel(const float* __restrict__ x,
                             const float* __restrict__ axis, int T) {
    int tid = threadIdx.x;
    KS acc[9];
#pragma unroll
    for (int k = 0; k < 9; k++) { acc[k].s = 0.f; acc[k].c = 0.f; }

    for (int b = tid; b < RBLK; b += 256)
#pragma unroll
        for (int k = 0; k < 9; k++) ks_add(acc[k], g_part[b * 9 + k]);

    int lane = tid & 31, wid = tid >> 5;
#pragma unroll
    for (int off = 16; off; off >>= 1)
#pragma unroll
        for (int k = 0; k < 9; k++) {
            float s2 = __shfl_down_sync(0xffffffffu, acc[k].s, off);
            float c2 = __shfl_down_sync(0xffffffffu, acc[k].c, off);
            acc[k] = ks_comb(acc[k], s2, c2);
        }

    __shared__ float shs[8][9], shc[8][9];
    if (lane == 0)
#pragma unroll
        for (int k = 0; k < 9; k++) { shs[wid][k] = acc[k].s; shc[wid][k] = acc[k].c; }
    __syncthreads();

    if (tid == 0) {
        double S[9];
#pragma unroll
        for (int k = 0; k < 9; k++) {
            double v = 0.0;
#pragma unroll
            for (int w = 0; w < 8; w++)
                v += (double)shs[w][k] + (double)shc[w][k];
            S[k] = v;
        }
        double invT = 1.0 / (double)T;               // DDIV #1
        double mu0 = S[0] * invT, mu1 = S[1] * invT, mu2 = S[2] * invT;
        double c00 = S[3] - S[0] * mu0;
        double c01 = S[4] - S[0] * mu1;
        double c02 = S[5] - S[0] * mu2;
        double c11 = S[6] - S[1] * mu1;
        double c12 = S[7] - S[1] * mu2;
        double c22 = S[8] - S[2] * mu2;
        // positive scaling (1/(T-1)) does not change eigenvectors: skipped

        double sh3 = (c00 + c11 + c22) * (1.0 / 3.0);
        double d00 = c00 - sh3, d11 = c11 - sh3, d22 = c22 - sh3;
        double mx = fabs(d00);
        if (fabs(d11) > mx) mx = fabs(d11);
        if (fabs(d22) > mx) mx = fabs(d22);
        if (fabs(c01) > mx) mx = fabs(c01);
        if (fabs(c02) > mx) mx = fabs(c02);
        if (fabs(c12) > mx) mx = fabs(c12);
        double inv = (mx > 0.0) ? (1.0 / mx) : 1.0;  // DDIV #2

        float A[3][3];
        A[0][0] = (float)(d00 * inv);
        A[1][1] = (float)(d11 * inv);
        A[2][2] = (float)(d22 * inv);
        A[0][1] = A[1][0] = (float)(c01 * inv);
        A[0][2] = A[2][0] = (float)(c02 * inv);
        A[1][2] = A[2][1] = (float)(c12 * inv);

        float V[3][3] = {{1,0,0},{0,1,0},{0,0,1}};
#pragma unroll 1
        for (int sweep = 0; sweep < 4; sweep++) {
            for (int p = 0; p < 2; p++)
                for (int q = p + 1; q < 3; q++) {
                    float apq = A[p][q];
                    if (fabsf(apq) < 1e-30f) continue;
                    float tau = __fdividef(A[q][q] - A[p][p], 2.0f * apq);
                    float t = __fdividef((tau >= 0.0f) ? 1.0f : -1.0f,
                                         fabsf(tau) + sqrtf(1.0f + tau * tau));
                    float cth = rsqrtf(1.0f + t * t);
                    float sth = t * cth;
                    for (int r = 0; r < 3; r++) {
                        float arp = A[r][p], arq = A[r][q];
                        A[r][p] = cth * arp - sth * arq;
                        A[r][q] = sth * arp + cth * arq;
                    }
                    for (int cc = 0; cc < 3; cc++) {
                        float apc = A[p][cc], aqc = A[q][cc];
                        A[p][cc] = cth * apc - sth * aqc;
                        A[q][cc] = sth * apc + cth * aqc;
                    }
                    for (int r = 0; r < 3; r++) {
                        float vrp = V[r][p], vrq = V[r][q];
                        V[r][p] = cth * vrp - sth * vrq;
                        V[r][q] = sth * vrp + cth * vrq;
                    }
                }
        }
        int im = 0;
        if (A[1][1] > A[0][0]) im = 1;
        if (A[2][2] > A[im][im]) im = 2;
        float zx = V[0][im], zy = V[1][im], zz = V[2][im];

        float qx = x[3 * (size_t)T];
        float qy = x[4 * (size_t)T];
        float qz = x[5 * (size_t)T];
        float qw = x[6 * (size_t)T];
        float fx = 2.0f * (qx * qz + qw * qy);
        float fy = 2.0f * (qy * qz - qw * qx);
        float fz = 1.0f - 2.0f * (qx * qx + qy * qy);
        if (fx * zx + fy * zy + fz * zz < 0.0f) { zx = -zx; zy = -zy; zz = -zz; }

        float ux = axis[0], uy = axis[1], uz = axis[2];
        float rx = uy * zz - uz * zy;
        float ry = uz * zx - ux * zz;
        float rz = ux * zy - uy * zx;
        float fwx = ry * uz - rz * uy;
        float fwy = rz * ux - rx * uz;
        float fwz = rx * uy - ry * ux;

        g_B[0] = rx;  g_B[1] = ry;  g_B[2] = rz;
        g_B[3] = ux;  g_B[4] = uy;  g_B[5] = uz;
        g_B[6] = fwx; g_B[7] = fwy; g_B[8] = fwz;
        g_ref[0] = x[0]; g_ref[1] = x[(size_t)T]; g_ref[2] = x[2 * (size_t)T];
    }
}

// ---------------------------------------------------------------------------
// Stage 3: transform. Xpos rows via default-caching loads (L2-resident from
// the reduce pass), Add rows via __ldcs (no reuse), __stcs stores (don't
// evict cached Xpos with output).
// ---------------------------------------------------------------------------
__global__ void transform_vec_kernel(const float* __restrict__ x,
                                     float* __restrict__ out, int T) {
    int n4 = T >> 2;
    int base = (blockIdx.x * blockDim.x + threadIdx.x) * 2;
    if (base >= n4) return;
    int cnt = (base + 1 < n4) ? 2 : 1;

    float b00 = g_B[0], b01 = g_B[1], b02 = g_B[2];
    float b10 = g_B[3], b11 = g_B[4], b12 = g_B[5];
    float b20 = g_B[6], b21 = g_B[7], b22 = g_B[8];
    float r0 = g_ref[0], r1 = g_ref[1], r2 = g_ref[2];

    const float4* X = (const float4*)x;
    float4* O = (float4*)out;

    float4 p0[2], p1[2], p2[2], a0[2], a1[2], a2[2];
#pragma unroll
    for (int u = 0; u < 2; u++) {
        if (u >= cnt) break;
        int i = base + u;
        p0[u] = X[i];
        p1[u] = X[n4 + i];
        p2[u] = X[2 * n4 + i];
        a0[u] = __ldcs(&X[7 * n4 + i]);
        a1[u] = __ldcs(&X[8 * n4 + i]);
        a2[u] = __ldcs(&X[9 * n4 + i]);
    }
#pragma unroll
    for (int u = 0; u < 2; u++) {
        if (u >= cnt) break;
        int i = base + u;
        float4 o0, o1, o2;
#define TR(f) {                                                    \
        float dx = p0[u].f - r0, dy = p1[u].f - r1, dz = p2[u].f - r2; \
        o0.f = b00 * dx + b01 * dy + b02 * dz;                     \
        o1.f = b10 * dx + b11 * dy + b12 * dz;                     \
        o2.f = b20 * dx + b21 * dy + b22 * dz; }
        TR(x); TR(y); TR(z); TR(w);
#undef TR
        __stcs(&O[i],          o0);
        __stcs(&O[n4 + i],     o1);
        __stcs(&O[2 * n4 + i], o2);
        __stcs(&O[3 * n4 + i], a0[u]);
        __stcs(&O[4 * n4 + i], a1[u]);
        __stcs(&O[5 * n4 + i], a2[u]);
    }
}

__global__ void transform_sca_kernel(const float* __restrict__ x,
                                     float* __restrict__ out, int T) {
    size_t sT = (size_t)T;
    float b00 = g_B[0], b01 = g_B[1], b02 = g_B[2];
    float b10 = g_B[3], b11 = g_B[4], b12 = g_B[5];
    float b20 = g_B[6], b21 = g_B[7], b22 = g_B[8];
    float r0 = g_ref[0], r1 = g_ref[1], r2 = g_ref[2];
    for (int t = blockIdx.x * blockDim.x + threadIdx.x; t < T;
         t += gridDim.x * blockDim.x) {
        float dx = x[t] - r0, dy = x[sT + t] - r1, dz = x[2 * sT + t] - r2;
        out[t]          = b00 * dx + b01 * dy + b02 * dz;
        out[sT + t]     = b10 * dx + b11 * dy + b12 * dz;
        out[2 * sT + t] = b20 * dx + b21 * dy + b22 * dz;
        out[3 * sT + t] = x[7 * sT + t];
        out[4 * sT + t] = x[8 * sT + t];
        out[5 * sT + t] = x[9 * sT + t];
    }
}

extern "C" void kernel_launch(void* const* d_in, const int* in_sizes, int n_in,
                              void* d_out, int out_size) {
    const float* x = (const float*)d_in[0];
    const float* axis = (const float*)d_in[1];
    int T = in_sizes[0] / 10;

    if ((T & 3) == 0) {
        reduce_vec_kernel<<<RBLK, RTHR>>>(x, T);
        solve_kernel<<<1, 256>>>(x, axis, T);
        int n4 = T >> 2;
        int threads = (n4 + 1) / 2;
        int blocks = (threads + 255) / 256;
        transform_vec_kernel<<<blocks, 256>>>(x, (float*)d_out, T);
    } else {
        reduce_sca_kernel<<<RBLK, RTHR>>>(x, T);
        solve_kernel<<<1, 256>>>(x, axis, T);
        int blocks = (T + 255) / 256;
        if (blocks > 16384) blocks = 16384;
        transform_sca_kernel<<<blocks, 256>>>(x, (float*)d_out, T);
    }
}

// round 6
// speedup vs baseline: 2.7313x; 1.1510x over previous
#include <cuda_runtime.h>

#define RBLK 2048
#define RTHR 256

__device__ float g_part[RBLK * 9];
__device__ float g_B[9];
__device__ float g_ref[3];

// ---------------------------------------------------------------------------
// Stage 1: 9-way reduction over Xpos (rows 0-2) FUSED with the Add copy
// (rows 7-9 -> out rows 3-5). The copy is basis-independent, so it can run
// before the eigensolve. Xpos loads use default caching (stay L2-resident
// for stage 3); Add copy uses __ldcs/__stcs (no reuse, don't pollute L2).
// ---------------------------------------------------------------------------
__global__ void __launch_bounds__(RTHR) reduce_copy_kernel(
        const float* __restrict__ x, float* __restrict__ out, int T) {
    int n4 = T >> 2;
    const float4* X = (const float4*)x;
    float4* O = (float4*)out;

    float s[9];
#pragma unroll
    for (int k = 0; k < 9; k++) s[k] = 0.f;

    for (int i = blockIdx.x * blockDim.x + threadIdx.x; i < n4;
         i += gridDim.x * blockDim.x) {
        float4 a = X[i];
        float4 b = X[n4 + i];
        float4 c = X[2 * n4 + i];
        float4 d = __ldcs(&X[7 * n4 + i]);
        float4 e = __ldcs(&X[8 * n4 + i]);
        float4 f = __ldcs(&X[9 * n4 + i]);
        __stcs(&O[3 * n4 + i], d);
        __stcs(&O[4 * n4 + i], e);
        __stcs(&O[5 * n4 + i], f);
#define ACC(ax, bx, cx)                                   \
        s[0] += (ax); s[1] += (bx); s[2] += (cx);         \
        s[3] += (ax)*(ax); s[4] += (ax)*(bx);             \
        s[5] += (ax)*(cx); s[6] += (bx)*(bx);             \
        s[7] += (bx)*(cx); s[8] += (cx)*(cx);
        ACC(a.x, b.x, c.x); ACC(a.y, b.y, c.y);
        ACC(a.z, b.z, c.z); ACC(a.w, b.w, c.w);
#undef ACC
    }

    int lane = threadIdx.x & 31, wid = threadIdx.x >> 5;
#pragma unroll
    for (int off = 16; off; off >>= 1)
#pragma unroll
        for (int k = 0; k < 9; k++)
            s[k] += __shfl_down_sync(0xffffffffu, s[k], off);

    __shared__ float sh[RTHR / 32][9];
    if (lane == 0)
#pragma unroll
        for (int k = 0; k < 9; k++) sh[wid][k] = s[k];
    __syncthreads();
    if (wid == 0) {
#pragma unroll
        for (int k = 0; k < 9; k++)
            s[k] = (lane < RTHR / 32) ? sh[lane][k] : 0.f;
#pragma unroll
        for (int off = 4; off; off >>= 1)
#pragma unroll
            for (int k = 0; k < 9; k++)
                s[k] += __shfl_down_sync(0xffffffffu, s[k], off);
        if (lane == 0)
#pragma unroll
            for (int k = 0; k < 9; k++)
                g_part[blockIdx.x * 9 + k] = s[k];
    }
}

// Scalar fallback (T % 4 != 0): reduce + copy
__global__ void reduce_copy_sca_kernel(const float* __restrict__ x,
                                       float* __restrict__ out, int T) {
    size_t sT = (size_t)T;
    float s[9];
#pragma unroll
    for (int k = 0; k < 9; k++) s[k] = 0.f;
    for (int t = blockIdx.x * blockDim.x + threadIdx.x; t < T;
         t += gridDim.x * blockDim.x) {
        float ax = x[t], bx = x[sT + t], cx = x[2 * sT + t];
        s[0]+=ax; s[1]+=bx; s[2]+=cx; s[3]+=ax*ax; s[4]+=ax*bx;
        s[5]+=ax*cx; s[6]+=bx*bx; s[7]+=bx*cx; s[8]+=cx*cx;
        out[3 * sT + t] = x[7 * sT + t];
        out[4 * sT + t] = x[8 * sT + t];
        out[5 * sT + t] = x[9 * sT + t];
    }
    int lane = threadIdx.x & 31, wid = threadIdx.x >> 5;
#pragma unroll
    for (int off = 16; off; off >>= 1)
#pragma unroll
        for (int k = 0; k < 9; k++)
            s[k] += __shfl_down_sync(0xffffffffu, s[k], off);
    __shared__ float sh[RTHR / 32][9];
    if (lane == 0)
#pragma unroll
        for (int k = 0; k < 9; k++) sh[wid][k] = s[k];
    __syncthreads();
    if (wid == 0) {
#pragma unroll
        for (int k = 0; k < 9; k++)
            s[k] = (lane < RTHR / 32) ? sh[lane][k] : 0.f;
#pragma unroll
        for (int off = 4; off; off >>= 1)
#pragma unroll
            for (int k = 0; k < 9; k++)
                s[k] += __shfl_down_sync(0xffffffffu, s[k], off);
        if (lane == 0)
#pragma unroll
            for (int k = 0; k < 9; k++)
                g_part[blockIdx.x * 9 + k] = s[k];
    }
}

// ---------------------------------------------------------------------------
// Compensated fp32 accumulation
// ---------------------------------------------------------------------------
struct KS { float s, c; };

__device__ __forceinline__ void ks_add(KS& a, float v) {
    float t  = a.s + v;
    float bp = t - a.s;
    float err = (a.s - (t - bp)) + (v - bp);
    a.c += err;
    a.s  = t;
}
__device__ __forceinline__ KS ks_comb(KS a, float s2, float c2) {
    float t  = a.s + s2;
    float bp = t - a.s;
    float err = (a.s - (t - bp)) + (s2 - bp);
    KS r; r.s = t; r.c = a.c + c2 + err;
    return r;
}

// ---------------------------------------------------------------------------
// Stage 2: final sum; covariance with 2 fp64 divides; scaled fp32 Jacobi.
// ---------------------------------------------------------------------------
__global__ void solve_kernel(const float* __restrict__ x,
                             const float* __restrict__ axis, int T) {
    int tid = threadIdx.x;
    KS acc[9];
#pragma unroll
    for (int k = 0; k < 9; k++) { acc[k].s = 0.f; acc[k].c = 0.f; }

    for (int b = tid; b < RBLK; b += 256)
#pragma unroll
        for (int k = 0; k < 9; k++) ks_add(acc[k], g_part[b * 9 + k]);

    int lane = tid & 31, wid = tid >> 5;
#pragma unroll
    for (int off = 16; off; off >>= 1)
#pragma unroll
        for (int k = 0; k < 9; k++) {
            float s2 = __shfl_down_sync(0xffffffffu, acc[k].s, off);
            float c2 = __shfl_down_sync(0xffffffffu, acc[k].c, off);
            acc[k] = ks_comb(acc[k], s2, c2);
        }

    __shared__ float shs[8][9], shc[8][9];
    if (lane == 0)
#pragma unroll
        for (int k = 0; k < 9; k++) { shs[wid][k] = acc[k].s; shc[wid][k] = acc[k].c; }
    __syncthreads();

    if (tid == 0) {
        double S[9];
#pragma unroll
        for (int k = 0; k < 9; k++) {
            double v = 0.0;
#pragma unroll
            for (int w = 0; w < 8; w++)
                v += (double)shs[w][k] + (double)shc[w][k];
            S[k] = v;
        }
        double invT = 1.0 / (double)T;               // DDIV #1
        double mu0 = S[0] * invT, mu1 = S[1] * invT, mu2 = S[2] * invT;
        double c00 = S[3] - S[0] * mu0;
        double c01 = S[4] - S[0] * mu1;
        double c02 = S[5] - S[0] * mu2;
        double c11 = S[6] - S[1] * mu1;
        double c12 = S[7] - S[1] * mu2;
        double c22 = S[8] - S[2] * mu2;

        double sh3 = (c00 + c11 + c22) * (1.0 / 3.0);
        double d00 = c00 - sh3, d11 = c11 - sh3, d22 = c22 - sh3;
        double mx = fabs(d00);
        if (fabs(d11) > mx) mx = fabs(d11);
        if (fabs(d22) > mx) mx = fabs(d22);
        if (fabs(c01) > mx) mx = fabs(c01);
        if (fabs(c02) > mx) mx = fabs(c02);
        if (fabs(c12) > mx) mx = fabs(c12);
        double inv = (mx > 0.0) ? (1.0 / mx) : 1.0;  // DDIV #2

        float A[3][3];
        A[0][0] = (float)(d00 * inv);
        A[1][1] = (float)(d11 * inv);
        A[2][2] = (float)(d22 * inv);
        A[0][1] = A[1][0] = (float)(c01 * inv);
        A[0][2] = A[2][0] = (float)(c02 * inv);
        A[1][2] = A[2][1] = (float)(c12 * inv);

        float V[3][3] = {{1,0,0},{0,1,0},{0,0,1}};
#pragma unroll 1
        for (int sweep = 0; sweep < 4; sweep++) {
            for (int p = 0; p < 2; p++)
                for (int q = p + 1; q < 3; q++) {
                    float apq = A[p][q];
                    if (fabsf(apq) < 1e-30f) continue;
                    float tau = __fdividef(A[q][q] - A[p][p], 2.0f * apq);
                    float t = __fdividef((tau >= 0.0f) ? 1.0f : -1.0f,
                                         fabsf(tau) + sqrtf(1.0f + tau * tau));
                    float cth = rsqrtf(1.0f + t * t);
                    float sth = t * cth;
                    for (int r = 0; r < 3; r++) {
                        float arp = A[r][p], arq = A[r][q];
                        A[r][p] = cth * arp - sth * arq;
                        A[r][q] = sth * arp + cth * arq;
                    }
                    for (int cc = 0; cc < 3; cc++) {
                        float apc = A[p][cc], aqc = A[q][cc];
                        A[p][cc] = cth * apc - sth * aqc;
                        A[q][cc] = sth * apc + cth * aqc;
                    }
                    for (int r = 0; r < 3; r++) {
                        float vrp = V[r][p], vrq = V[r][q];
                        V[r][p] = cth * vrp - sth * vrq;
                        V[r][q] = sth * vrp + cth * vrq;
                    }
                }
        }
        int im = 0;
        if (A[1][1] > A[0][0]) im = 1;
        if (A[2][2] > A[im][im]) im = 2;
        float zx = V[0][im], zy = V[1][im], zz = V[2][im];

        float qx = x[3 * (size_t)T];
        float qy = x[4 * (size_t)T];
        float qz = x[5 * (size_t)T];
        float qw = x[6 * (size_t)T];
        float fx = 2.0f * (qx * qz + qw * qy);
        float fy = 2.0f * (qy * qz - qw * qx);
        float fz = 1.0f - 2.0f * (qx * qx + qy * qy);
        if (fx * zx + fy * zy + fz * zz < 0.0f) { zx = -zx; zy = -zy; zz = -zz; }

        float ux = axis[0], uy = axis[1], uz = axis[2];
        float rx = uy * zz - uz * zy;
        float ry = uz * zx - ux * zz;
        float rz = ux * zy - uy * zx;
        float fwx = ry * uz - rz * uy;
        float fwy = rz * ux - rx * uz;
        float fwz = rx * uy - ry * ux;

        g_B[0] = rx;  g_B[1] = ry;  g_B[2] = rz;
        g_B[3] = ux;  g_B[4] = uy;  g_B[5] = uz;
        g_B[6] = fwx; g_B[7] = fwy; g_B[8] = fwz;
        g_ref[0] = x[0]; g_ref[1] = x[(size_t)T]; g_ref[2] = x[2 * (size_t)T];
    }
}

// ---------------------------------------------------------------------------
// Stage 3: transform only (Add copy already done in stage 1).
// Xpos reads should largely hit L2 (left resident by stage 1).
// ---------------------------------------------------------------------------
__global__ void __launch_bounds__(RTHR) transform_vec_kernel(
        const float* __restrict__ x, float* __restrict__ out, int T) {
    int n4 = T >> 2;
    int i = blockIdx.x * blockDim.x + threadIdx.x;
    if (i >= n4) return;

    float b00 = g_B[0], b01 = g_B[1], b02 = g_B[2];
    float b10 = g_B[3], b11 = g_B[4], b12 = g_B[5];
    float b20 = g_B[6], b21 = g_B[7], b22 = g_B[8];
    float r0 = g_ref[0], r1 = g_ref[1], r2 = g_ref[2];

    const float4* X = (const float4*)x;
    float4* O = (float4*)out;

    float4 p0 = X[i], p1 = X[n4 + i], p2 = X[2 * n4 + i];
    float4 o0, o1, o2;
#define TR(f) {                                           \
    float dx = p0.f - r0, dy = p1.f - r1, dz = p2.f - r2; \
    o0.f = b00 * dx + b01 * dy + b02 * dz;                \
    o1.f = b10 * dx + b11 * dy + b12 * dz;                \
    o2.f = b20 * dx + b21 * dy + b22 * dz; }
    TR(x); TR(y); TR(z); TR(w);
#undef TR
    __stcs(&O[i],          o0);
    __stcs(&O[n4 + i],     o1);
    __stcs(&O[2 * n4 + i], o2);
}

__global__ void transform_sca_kernel(const float* __restrict__ x,
                                     float* __restrict__ out, int T) {
    size_t sT = (size_t)T;
    float b00 = g_B[0], b01 = g_B[1], b02 = g_B[2];
    float b10 = g_B[3], b11 = g_B[4], b12 = g_B[5];
    float b20 = g_B[6], b21 = g_B[7], b22 = g_B[8];
    float r0 = g_ref[0], r1 = g_ref[1], r2 = g_ref[2];
    for (int t = blockIdx.x * blockDim.x + threadIdx.x; t < T;
         t += gridDim.x * blockDim.x) {
        float dx = x[t] - r0, dy = x[sT + t] - r1, dz = x[2 * sT + t] - r2;
        out[t]          = b00 * dx + b01 * dy + b02 * dz;
        out[sT + t]     = b10 * dx + b11 * dy + b12 * dz;
        out[2 * sT + t] = b20 * dx + b21 * dy + b22 * dz;
    }
}

extern "C" void kernel_launch(void* const* d_in, const int* in_sizes, int n_in,
                              void* d_out, int out_size) {
    const float* x = (const float*)d_in[0];
    const float* axis = (const float*)d_in[1];
    int T = in_sizes[0] / 10;

    if ((T & 3) == 0) {
        reduce_copy_kernel<<<RBLK, RTHR>>>(x, (float*)d_out, T);
        solve_kernel<<<1, 256>>>(x, axis, T);
        int n4 = T >> 2;
        int blocks = (n4 + RTHR - 1) / RTHR;
        transform_vec_kernel<<<blocks, RTHR>>>(x, (float*)d_out, T);
    } else {
        reduce_copy_sca_kernel<<<RBLK, RTHR>>>(x, (float*)d_out, T);
        solve_kernel<<<1, 256>>>(x, axis, T);
        int blocks = (T + RTHR - 1) / RTHR;
        if (blocks > 16384) blocks = 16384;
        transform_sca_kernel<<<blocks, RTHR>>>(x, (float*)d_out, T);
    }
}